// round 1
// baseline (speedup 1.0000x reference)
#include <cuda_runtime.h>

// SelfConnectionIntro: e3nn FCTP with in2 = 16 x 0e scalars.
// out_l[z,w,k] = alpha_l * sum_{u,v} x_l[z,u,k] * operand[z,v] * W_l[u,v,w]
//
// Scheme (per path): thread = output channel w (threadIdx.x), y-groups each own
// ZT=8 nodes. Inner loop over u: load 16 W values W[u,0:16,w] (coalesced across
// threads), then per node: s = dot16(operand[z], Wv); acc[z][k] += x[z,u,k]*s.
// W reused ZT times per load -> L2-resident streaming; x/operand staged in smem.

#define ZT 8

template<int U, int WD, int D, int YS>
__global__ __launch_bounds__(WD * YS)
void fctp_path_kernel(const float* __restrict__ x,
                      const float* __restrict__ opr,
                      const float* __restrict__ Wt,
                      float* __restrict__ out,
                      int Z, int xoff, float alpha)
{
    __shared__ float xs[YS][ZT][U * D];
    __shared__ float ops[YS][ZT][16];

    const int w  = threadIdx.x;
    const int ty = threadIdx.y;
    const long long zbase = ((long long)blockIdx.x * YS + ty) * ZT;

    int zn = 0;
    if (zbase < Z) {
        long long rem = (long long)Z - zbase;
        zn = rem < ZT ? (int)rem : ZT;
        // stage x slice [ZT, U*D] and operand [ZT, 16] for this y-group
        for (int i = w; i < ZT * U * D; i += WD) {
            int zl = i / (U * D);
            int c  = i % (U * D);
            xs[ty][zl][c] = (zl < zn) ? x[(zbase + zl) * 480 + xoff + c] : 0.0f;
        }
        for (int i = w; i < ZT * 16; i += WD) {
            int zl = i >> 4;
            int v  = i & 15;
            ops[ty][zl][v] = (zl < zn) ? opr[(zbase + zl) * 16 + v] : 0.0f;
        }
    }
    __syncthreads();
    if (zbase >= Z) return;

    float acc[ZT][D];
#pragma unroll
    for (int z = 0; z < ZT; z++)
#pragma unroll
        for (int k = 0; k < D; k++) acc[z][k] = 0.0f;

    for (int u = 0; u < U; u++) {
        float wv[16];
#pragma unroll
        for (int v = 0; v < 16; v++)
            wv[v] = Wt[(u * 16 + v) * WD + w];   // coalesced across threads

#pragma unroll
        for (int z = 0; z < ZT; z++) {
            float s = 0.0f;
#pragma unroll
            for (int v = 0; v < 16; v++)
                s = fmaf(ops[ty][z][v], wv[v], s);
#pragma unroll
            for (int k = 0; k < D; k++)
                acc[z][k] = fmaf(xs[ty][z][u * D + k], s, acc[z][k]);
        }
    }

    for (int z = 0; z < zn; z++) {
#pragma unroll
        for (int k = 0; k < D; k++)
            out[(zbase + z) * 480 + xoff + w * D + k] = alpha * acc[z][k];
    }
}

extern "C" void kernel_launch(void* const* d_in, const int* in_sizes, int n_in,
                              void* d_out, int out_size)
{
    const float* x   = (const float*)d_in[0];
    const float* opr = (const float*)d_in[1];
    const float* w0  = (const float*)d_in[2];
    const float* w1  = (const float*)d_in[3];
    const float* w2  = (const float*)d_in[4];
    float* out = (float*)d_out;

    const int Z = in_sizes[1] / 16;  // operand is [Z, 16]

    // alpha = 1/sqrt(mul_in * n_species)
    const float a0 = 0.022097086912079608f;  // 1/sqrt(2048)
    const float a1 = 0.03125f;               // 1/sqrt(1024)
    const float a2 = 0.044194173824159216f;  // 1/sqrt(512)

    // path0: u=128, w=128, d=1; offsets 0
    {
        dim3 blk(128, 2);
        int nodes_per_cta = 2 * ZT;
        int grid = (Z + nodes_per_cta - 1) / nodes_per_cta;
        fctp_path_kernel<128, 128, 1, 2><<<grid, blk>>>(x, opr, w0, out, Z, 0, a0);
    }
    // path1: u=64, w=64, d=3; offset 128
    {
        dim3 blk(64, 4);
        int nodes_per_cta = 4 * ZT;
        int grid = (Z + nodes_per_cta - 1) / nodes_per_cta;
        fctp_path_kernel<64, 64, 3, 4><<<grid, blk>>>(x, opr, w1, out, Z, 128, a1);
    }
    // path2: u=32, w=32, d=5; offset 320
    {
        dim3 blk(32, 8);
        int nodes_per_cta = 8 * ZT;
        int grid = (Z + nodes_per_cta - 1) / nodes_per_cta;
        fctp_path_kernel<32, 32, 5, 8><<<grid, blk>>>(x, opr, w2, out, Z, 320, a2);
    }
}

// round 2
// speedup vs baseline: 1.4369x; 1.4369x over previous
#include <cuda_runtime.h>

// SelfConnectionIntro: e3nn FCTP, in2 = 16 x 0e scalars.
// out_l[z,w,k] = alpha_l * sum_{u,v} x_l[z,u,k] * operand[z,v] * W_l[u,v,w]
//
// R2 scheme: thread = output channel w; each thread owns ZT nodes packed as
// ZT/2 f32x2 lane-pairs. operand[z,0:16] is register-resident (packed pairs),
// W is staged chunk-wise in smem and read once per (u, thread), duplicated
// into both f32x2 lanes with one mov.b64. All heavy math is FFMA2
// (fma.rn.f32x2) -> 2x fp32 FMA per issue slot, bit-exact fp32.

typedef unsigned long long u64;

__device__ __forceinline__ u64 pack2(float lo, float hi) {
    u64 d; asm("mov.b64 %0, {%1, %2};" : "=l"(d) : "f"(lo), "f"(hi)); return d;
}
__device__ __forceinline__ void unpack2(u64 d, float& lo, float& hi) {
    asm("mov.b64 {%0, %1}, %2;" : "=f"(lo), "=f"(hi) : "l"(d));
}
__device__ __forceinline__ u64 fma2(u64 a, u64 b, u64 c) {
    u64 d; asm("fma.rn.f32x2 %0, %1, %2, %3;" : "=l"(d) : "l"(a), "l"(b), "l"(c));
    return d;
}

template<int U, int WD, int D, int YS, int ZT, int UC>
__global__ __launch_bounds__(WD * YS)
void fctp2_kernel(const float* __restrict__ x,
                  const float* __restrict__ opr,
                  const float* __restrict__ Wg,
                  float* __restrict__ out,
                  int Z, int xoff, float alpha)
{
    constexpr int ZP = ZT / 2;
    extern __shared__ char smraw[];
    float*  Ws = (float*)smraw;                                  // [UC][16][WD]
    float2* xs = (float2*)(smraw + (size_t)UC * 16 * WD * 4);    // [YS][U*D][ZP]

    const int w    = threadIdx.x;
    const int ty   = threadIdx.y;
    const int tid  = ty * WD + w;
    const int nthr = WD * YS;
    const long long zcta  = (long long)blockIdx.x * (YS * ZT);
    const long long zbase = zcta + (long long)ty * ZT;

    // Stage x slice for all YS*ZT nodes, packed as (z even, z odd) float2.
    for (int i = tid; i < YS * ZT * U * D; i += nthr) {
        int zl = i / (U * D), c = i % (U * D);
        long long z = zcta + zl;
        float v = (z < Z) ? x[z * 480 + xoff + c] : 0.0f;
        int gy = zl / ZT, zz = zl % ZT;
        ((float*)&xs[((size_t)gy * (U * D) + c) * ZP + (zz >> 1)])[zz & 1] = v;
    }

    // operand -> registers, packed per z-pair. Warp-uniform addresses (cheap).
    u64 op2[ZP][16];
#pragma unroll
    for (int zp = 0; zp < ZP; zp++) {
        long long z0 = zbase + 2 * zp, z1 = z0 + 1;
#pragma unroll
        for (int v = 0; v < 16; v++) {
            float a0 = (z0 < Z) ? opr[z0 * 16 + v] : 0.0f;
            float a1 = (z1 < Z) ? opr[z1 * 16 + v] : 0.0f;
            op2[zp][v] = pack2(a0, a1);
        }
    }

    u64 acc2[ZP][D];
#pragma unroll
    for (int zp = 0; zp < ZP; zp++)
#pragma unroll
        for (int k = 0; k < D; k++) acc2[zp][k] = 0ull;

    for (int uc = 0; uc < U; uc += UC) {
        __syncthreads();
        {   // cooperative W chunk load (float4, coalesced)
            const float4* src = (const float4*)(Wg + (size_t)uc * 16 * WD);
            float4* dst = (float4*)Ws;
            for (int i = tid; i < UC * 16 * WD / 4; i += nthr) dst[i] = src[i];
        }
        __syncthreads();

#pragma unroll 4
        for (int uu = 0; uu < UC; uu++) {
            u64 wv2[16];
#pragma unroll
            for (int v = 0; v < 16; v++) {
                float t = Ws[((size_t)uu * 16 + v) * WD + w];
                wv2[v] = pack2(t, t);
            }
            u64 s2[ZP];
#pragma unroll
            for (int zp = 0; zp < ZP; zp++) s2[zp] = 0ull;
#pragma unroll
            for (int v = 0; v < 16; v++)
#pragma unroll
                for (int zp = 0; zp < ZP; zp++)
                    s2[zp] = fma2(op2[zp][v], wv2[v], s2[zp]);

            const int u = uc + uu;
#pragma unroll
            for (int zp = 0; zp < ZP; zp++)
#pragma unroll
                for (int k = 0; k < D; k++) {
                    u64 xv = *(const u64*)&xs[((size_t)ty * (U * D) + u * D + k) * ZP + zp];
                    acc2[zp][k] = fma2(xv, s2[zp], acc2[zp][k]);
                }
        }
    }

    // Store (scale by alpha)
#pragma unroll
    for (int zp = 0; zp < ZP; zp++) {
        long long z0 = zbase + 2 * zp, z1 = z0 + 1;
#pragma unroll
        for (int k = 0; k < D; k++) {
            float lo, hi; unpack2(acc2[zp][k], lo, hi);
            if (z0 < Z) out[z0 * 480 + xoff + w * D + k] = alpha * lo;
            if (z1 < Z) out[z1 * 480 + xoff + w * D + k] = alpha * hi;
        }
    }
}

extern "C" void kernel_launch(void* const* d_in, const int* in_sizes, int n_in,
                              void* d_out, int out_size)
{
    const float* x   = (const float*)d_in[0];
    const float* opr = (const float*)d_in[1];
    const float* w0  = (const float*)d_in[2];
    const float* w1  = (const float*)d_in[3];
    const float* w2  = (const float*)d_in[4];
    float* out = (float*)d_out;

    const int Z = in_sizes[1] / 16;

    const float a0 = 0.022097086912079608f;  // 1/sqrt(128*16)
    const float a1 = 0.03125f;               // 1/sqrt(64*16)
    const float a2 = 0.044194173824159216f;  // 1/sqrt(32*16)

    // path0: U=128, WD=128, D=1, YS=2, ZT=8, UC=16  -> 256 thr, 16 z/CTA
    {
        constexpr int SM = 16*16*128*4 + 2*128*4*8;   // 139264 B
        cudaFuncSetAttribute(fctp2_kernel<128,128,1,2,8,16>,
                             cudaFuncAttributeMaxDynamicSharedMemorySize, SM);
        dim3 blk(128, 2);
        int grid = (Z + 15) / 16;
        fctp2_kernel<128,128,1,2,8,16><<<grid, blk, SM>>>(x, opr, w0, out, Z, 0, a0);
    }
    // path1: U=64, WD=64, D=3, YS=4, ZT=4, UC=16 -> 256 thr, 16 z/CTA
    {
        constexpr int SM = 16*16*64*4 + 4*192*2*8;    // 77824 B
        cudaFuncSetAttribute(fctp2_kernel<64,64,3,4,4,16>,
                             cudaFuncAttributeMaxDynamicSharedMemorySize, SM);
        dim3 blk(64, 4);
        int grid = (Z + 15) / 16;
        fctp2_kernel<64,64,3,4,4,16><<<grid, blk, SM>>>(x, opr, w1, out, Z, 128, a1);
    }
    // path2: U=32, WD=32, D=5, YS=8, ZT=4, UC=32 -> 256 thr, 32 z/CTA
    {
        constexpr int SM = 32*16*32*4 + 8*160*2*8;    // 86016 B
        cudaFuncSetAttribute(fctp2_kernel<32,32,5,8,4,32>,
                             cudaFuncAttributeMaxDynamicSharedMemorySize, SM);
        dim3 blk(32, 8);
        int grid = (Z + 31) / 32;
        fctp2_kernel<32,32,5,8,4,32><<<grid, blk, SM>>>(x, opr, w2, out, Z, 320, a2);
    }
}

// round 4
// speedup vs baseline: 2.5996x; 1.8092x over previous
#include <cuda_runtime.h>
#include <cuda_bf16.h>
#include <cstdint>

// SelfConnectionIntro via baseline-PTX HMMA (mma.sync m16n8k16 bf16):
// out_l[z,w,k] = alpha * sum_v opr[z,v] * (x_l[:,:,k] @ W_l[:,v,:])[z,w]
// Split-bf16 (3 terms: AhBh + AhBl + AlBh) for fp32-class accuracy.
// A (=x tile) split hi/lo in smem, ldmatrix. B (=W) pre-fragmented in global
// to the per-lane HMMA B layout -> coalesced LDG.64, L1-resident.
// opr applied in a register epilogue on the HMMA accumulators.

__device__ __forceinline__ uint32_t smem_u32(const void* p) {
    uint32_t a;
    asm("{ .reg .u64 t; cvta.to.shared.u64 t, %1; cvt.u32.u64 %0, t; }" : "=r"(a) : "l"(p));
    return a;
}
__device__ __forceinline__ void ldmat_x4(uint32_t r[4], uint32_t a) {
    asm volatile("ldmatrix.sync.aligned.m8n8.x4.shared.b16 {%0,%1,%2,%3}, [%4];"
                 : "=r"(r[0]), "=r"(r[1]), "=r"(r[2]), "=r"(r[3]) : "r"(a));
}
__device__ __forceinline__ void mma16816(float d[4], const uint32_t a[4],
                                         uint32_t b0, uint32_t b1) {
    asm volatile("mma.sync.aligned.m16n8k16.row.col.f32.bf16.bf16.f32 "
                 "{%0,%1,%2,%3},{%4,%5,%6,%7},{%8,%9},{%0,%1,%2,%3};"
                 : "+f"(d[0]), "+f"(d[1]), "+f"(d[2]), "+f"(d[3])
                 : "r"(a[0]), "r"(a[1]), "r"(a[2]), "r"(a[3]), "r"(b0), "r"(b1));
}

// Pre-fragmented B images: [h(hi/lo)][v(16)][ks][nb][lane(32)] as uint2 (b0,b1).
__device__ uint2 BIMG0[2 * 16 * 8 * 16 * 32];  // path0 U=128 N=128 (1 MB)
__device__ uint2 BIMG1[2 * 16 * 4 *  8 * 32];  // path1 U=64  N=64
__device__ uint2 BIMG2[2 * 16 * 2 *  4 * 32];  // path2 U=32  N=32

// W layout [U][16][NTOT]. B frag (k16 x n8): lane t, reg r, half hh:
//   u = ks*16 + 2*(t&3) + hh + r*8 ; n = nb*8 + t/4 ; value = W[u][v][n].
template<int U, int NTOT>
__global__ void prepB(const float* __restrict__ W, uint2* __restrict__ dst) {
    constexpr int KS = U / 16, NBT = NTOT / 8;
    const int total = 2 * 16 * KS * NBT * 32;
    for (int i = blockIdx.x * blockDim.x + threadIdx.x; i < total;
         i += gridDim.x * blockDim.x) {
        int lane = i & 31, r1 = i >> 5;
        int nbg = r1 % NBT; r1 /= NBT;
        int ks = r1 % KS;  r1 /= KS;
        int v = r1 & 15, h = r1 >> 4;
        int n = nbg * 8 + (lane >> 2);
        uint32_t wr[2];
#pragma unroll
        for (int r = 0; r < 2; r++) {
            uint32_t word = 0;
#pragma unroll
            for (int hh = 0; hh < 2; hh++) {
                int u = ks * 16 + 2 * (lane & 3) + hh + r * 8;
                float f = W[((size_t)u * 16 + v) * NTOT + n];
                __nv_bfloat16 bh = __float2bfloat16(f);
                __nv_bfloat16 bo = h ? __float2bfloat16(f - __bfloat162float(bh)) : bh;
                uint16_t bits = *(uint16_t*)&bo;
                word |= (uint32_t)bits << (hh * 16);
            }
            wr[r] = word;
        }
        dst[i] = make_uint2(wr[0], wr[1]);
    }
}

// Main kernel: CTA = 128-node tile x NTOT output channels, one k-component.
template<int U, int NTOT, int D, int WM, int WN, int MW, int NBW>
__global__ __launch_bounds__(WM * WN * 32)
void fctp_hmma(const float* __restrict__ x, const float* __restrict__ opr,
               const uint2* __restrict__ Bimg, float* __restrict__ out,
               int Z, int xoff, float alpha)
{
    constexpr int KS = U / 16, NBT = NTOT / 8, RS = U + 8;   // padded row (elems)
    constexpr int NT = WM * WN * 32;
    constexpr int XB = 128 * RS * 2;                          // one bf16 x-tile

    extern __shared__ char smraw[];
    __nv_bfloat16* xh = (__nv_bfloat16*)smraw;
    __nv_bfloat16* xl = (__nv_bfloat16*)(smraw + XB);
    float* ops = (float*)(smraw + 2 * XB);                    // [128][17]

    const int tid = threadIdx.x, lane = tid & 31, wid = tid >> 5;
    const int wm = wid % WM, wn = wid / WM;
    const int moff = wm * MW * 16, wnoff = wn * NBW * 8;
    const int kc = blockIdx.y;
    const int zbase = blockIdx.x * 128;

    // Stage x (split hi/lo bf16) and opr.
    for (int e = tid; e < 128 * U; e += NT) {
        int zl = e / U, u = e % U;
        int z = zbase + zl;
        float v = (z < Z) ? x[(size_t)z * 480 + xoff + u * D + kc] : 0.0f;
        __nv_bfloat16 h = __float2bfloat16(v);
        xh[zl * RS + u] = h;
        xl[zl * RS + u] = __float2bfloat16(v - __bfloat162float(h));
    }
    for (int e = tid; e < 128 * 16; e += NT) {
        int zl = e >> 4, v = e & 15;
        int z = zbase + zl;
        ops[zl * 17 + v] = (z < Z) ? opr[(size_t)z * 16 + v] : 0.0f;
    }
    __syncthreads();

    const uint32_t xhB = smem_u32(xh), xlB = smem_u32(xl);
    // ldmatrix per-lane address: rows lane&15, +16B col offset for lanes>=16.
    const uint32_t aLane = (uint32_t)(moff + (lane & 15)) * (RS * 2) + ((lane >> 4) << 4);
    const uint2* pB = Bimg + (size_t)(wn * NBW) * 32 + lane;

    float acc[MW * NBW * 4];
#pragma unroll
    for (int i = 0; i < MW * NBW * 4; i++) acc[i] = 0.0f;

    uint32_t A[2][MW][4];
    uint2    Bf[2][NBW];

    auto pfA = [&](int buf, int hsel, int ks) {
        uint32_t base = (hsel ? xlB : xhB) + aLane + ks * 32;
#pragma unroll
        for (int mb = 0; mb < MW; mb++) ldmat_x4(A[buf][mb], base + mb * 16 * RS * 2);
    };
    auto pfB = [&](int buf, int himg, int v, int ks) {
        const uint2* p = pB + (size_t)((himg * 16 + v) * KS + ks) * (NBT * 32);
#pragma unroll
        for (int j = 0; j < NBW; j++) Bf[buf][j] = p[j * 32];
    };

    pfA(0, 0, 0);
    pfB(0, 0, 0, 0);

    for (int v = 0; v < 16; v++) {
        float d[MW * NBW * 4];
#pragma unroll
        for (int i = 0; i < MW * NBW * 4; i++) d[i] = 0.0f;

#pragma unroll
        for (int t = 0; t < 3; t++) {
#pragma unroll
            for (int ks = 0; ks < KS; ks++) {
                const int s = t * KS + ks, cur = s & 1, nxt = cur ^ 1;
                // prefetch next (term, kstep) [wraps to v+1]
                int nt = t, nks = ks + 1; bool wv = false;
                if (nks == KS) { nks = 0; nt = t + 1; if (nt == 3) { nt = 0; wv = true; } }
                if (!(wv && v == 15)) {
                    int nv = wv ? v + 1 : v;
                    pfA(nxt, (nt == 2) ? 1 : 0, nks);
                    pfB(nxt, (nt == 1) ? 1 : 0, nv, nks);
                }
#pragma unroll
                for (int mb = 0; mb < MW; mb++)
#pragma unroll
                    for (int j = 0; j < NBW; j++)
                        mma16816(&d[(mb * NBW + j) * 4], A[cur][mb],
                                 Bf[cur][j].x, Bf[cur][j].y);
            }
        }
        // epilogue: acc += opr[z,v] * d (opr broadcast from smem, fp32-exact)
#pragma unroll
        for (int mb = 0; mb < MW; mb++) {
            float o0 = ops[(moff + mb * 16 + (lane >> 2)) * 17 + v];
            float o1 = ops[(moff + mb * 16 + (lane >> 2) + 8) * 17 + v];
#pragma unroll
            for (int j = 0; j < NBW; j++) {
                float* dd = &d[(mb * NBW + j) * 4];
                float* aa = &acc[(mb * NBW + j) * 4];
                aa[0] = fmaf(o0, dd[0], aa[0]);
                aa[1] = fmaf(o0, dd[1], aa[1]);
                aa[2] = fmaf(o1, dd[2], aa[2]);
                aa[3] = fmaf(o1, dd[3], aa[3]);
            }
        }
    }

    // store
#pragma unroll
    for (int mb = 0; mb < MW; mb++) {
        int z0 = zbase + moff + mb * 16 + (lane >> 2);
#pragma unroll
        for (int j = 0; j < NBW; j++) {
            int w = wnoff + j * 8 + 2 * (lane & 3);
            float* aa = &acc[(mb * NBW + j) * 4];
            if (D == 1) {
                if (z0 < Z)
                    *(float2*)&out[(size_t)z0 * 480 + xoff + w] =
                        make_float2(alpha * aa[0], alpha * aa[1]);
                if (z0 + 8 < Z)
                    *(float2*)&out[(size_t)(z0 + 8) * 480 + xoff + w] =
                        make_float2(alpha * aa[2], alpha * aa[3]);
            } else {
                if (z0 < Z) {
                    out[(size_t)z0 * 480 + xoff + w * D + kc]       = alpha * aa[0];
                    out[(size_t)z0 * 480 + xoff + (w + 1) * D + kc] = alpha * aa[1];
                }
                if (z0 + 8 < Z) {
                    out[(size_t)(z0 + 8) * 480 + xoff + w * D + kc]       = alpha * aa[2];
                    out[(size_t)(z0 + 8) * 480 + xoff + (w + 1) * D + kc] = alpha * aa[3];
                }
            }
        }
    }
}

extern "C" void kernel_launch(void* const* d_in, const int* in_sizes, int n_in,
                              void* d_out, int out_size)
{
    const float* x   = (const float*)d_in[0];
    const float* opr = (const float*)d_in[1];
    const float* w0  = (const float*)d_in[2];
    const float* w1  = (const float*)d_in[3];
    const float* w2  = (const float*)d_in[4];
    float* out = (float*)d_out;

    const int Z  = in_sizes[1] / 16;
    const int GZ = (Z + 127) / 128;

    const float a0 = 0.022097086912079608f;  // 1/sqrt(128*16)
    const float a1 = 0.03125f;               // 1/sqrt(64*16)
    const float a2 = 0.044194173824159216f;  // 1/sqrt(32*16)

    void *p0, *p1, *p2;
    cudaGetSymbolAddress(&p0, BIMG0);
    cudaGetSymbolAddress(&p1, BIMG1);
    cudaGetSymbolAddress(&p2, BIMG2);

    prepB<128, 128><<<256, 256>>>(w0, (uint2*)p0);
    prepB< 64,  64><<< 64, 256>>>(w1, (uint2*)p1);
    prepB< 32,  32><<< 16, 256>>>(w2, (uint2*)p2);

    // path0: U=128, N=128, D=1; warps 4x2, warp tile m32 x n64
    {
        constexpr int SM = 2 * 128 * (128 + 8) * 2 + 128 * 17 * 4;  // 78336
        cudaFuncSetAttribute(fctp_hmma<128, 128, 1, 4, 2, 2, 8>,
                             cudaFuncAttributeMaxDynamicSharedMemorySize, SM);
        dim3 grid(GZ, 1);
        fctp_hmma<128, 128, 1, 4, 2, 2, 8><<<grid, 256, SM>>>(
            x, opr, (const uint2*)p0, out, Z, 0, a0);
    }
    // path1: U=64, N=64, D=3; warps 4x2, warp tile m32 x n32
    {
        constexpr int SM = 2 * 128 * (64 + 8) * 2 + 128 * 17 * 4;   // 45568
        cudaFuncSetAttribute(fctp_hmma<64, 64, 3, 4, 2, 2, 4>,
                             cudaFuncAttributeMaxDynamicSharedMemorySize, SM);
        dim3 grid(GZ, 3);
        fctp_hmma<64, 64, 3, 4, 2, 2, 4><<<grid, 256, SM>>>(
            x, opr, (const uint2*)p1, out, Z, 128, a1);
    }
    // path2: U=32, N=32, D=5; warps 8x1, warp tile m16 x n32
    {
        constexpr int SM = 2 * 128 * (32 + 8) * 2 + 128 * 17 * 4;   // 29184
        cudaFuncSetAttribute(fctp_hmma<32, 32, 5, 8, 1, 1, 4>,
                             cudaFuncAttributeMaxDynamicSharedMemorySize, SM);
        dim3 grid(GZ, 5);
        fctp_hmma<32, 32, 5, 8, 1, 1, 4><<<grid, 256, SM>>>(
            x, opr, (const uint2*)p2, out, Z, 320, a2);
    }
}